// round 7
// baseline (speedup 1.0000x reference)
#include <cuda_runtime.h>

// SpikeLayer LIF timestep, N = 12,845,056 fp32 elements, 5 inputs / 6 outputs.
// spikes ∈ {0,1}:
//   mem_out    = new_mem - spikes
//   counts_out = spikecounts + spikes
//   spiketrain = 0.5f * spikes
//   refrac_out = spikes ? 2.5f : refrac_until
//
// R4: persistent grid-stride kernel (1184 CTAs = 1 wave on 148 SMs) with a
// software-pipelined double buffer: iteration k+1's 5 loads are issued before
// iteration k's 6 stores, so the per-warp read stream never idles during the
// write phase. Eliminates the 10.6-wave structure of the flat launch.

#define TIME_C 0.5f
#define VTH_C 1.0f
#define REFRAC_SET 2.5f

struct In5 { float4 imp, m, ma, ru, sc; };

__device__ __forceinline__ void load5(
    const float4* __restrict__ impulse, const float4* __restrict__ mem,
    const float4* __restrict__ mem_acc, const float4* __restrict__ refrac_until,
    const float4* __restrict__ spikecounts, int i, In5& d)
{
    d.imp = impulse[i];
    d.m   = mem[i];
    d.ma  = mem_acc[i];
    d.ru  = refrac_until[i];
    d.sc  = spikecounts[i];
}

__device__ __forceinline__ void compute_store(
    const In5& d, float4* __restrict__ out, size_t nv, int i)
{
    float4 spikes, mem_out, ma_out, ru_out, sc_out, st_out;
    #pragma unroll
    for (int c = 0; c < 4; c++) {
        float impv = (&d.imp.x)[c];
        float mv   = (&d.m.x)[c];
        float mav  = (&d.ma.x)[c];
        float ruv  = (&d.ru.x)[c];
        float scv  = (&d.sc.x)[c];

        float masked  = (ruv > TIME_C) ? 0.0f : impv;
        float new_mem = mv + masked;
        float spk     = (new_mem >= VTH_C) ? 1.0f : 0.0f;

        (&spikes.x)[c]  = spk;
        (&mem_out.x)[c] = new_mem - spk;
        (&ma_out.x)[c]  = mav + masked;
        (&ru_out.x)[c]  = (spk != 0.0f) ? REFRAC_SET : ruv;
        (&sc_out.x)[c]  = scv + spk;
        (&st_out.x)[c]  = TIME_C * spk;
    }
    out[0 * nv + i] = spikes;
    out[1 * nv + i] = mem_out;
    out[2 * nv + i] = ma_out;
    out[3 * nv + i] = ru_out;
    out[4 * nv + i] = sc_out;
    out[5 * nv + i] = st_out;
}

__global__ void __launch_bounds__(256) spike_layer_kernel(
    const float4* __restrict__ impulse,
    const float4* __restrict__ mem,
    const float4* __restrict__ mem_acc,
    const float4* __restrict__ refrac_until,
    const float4* __restrict__ spikecounts,
    float4* __restrict__ out,   // 6 * nvec float4s
    int nvec)
{
    const int stride = gridDim.x * blockDim.x;
    int i = blockIdx.x * blockDim.x + threadIdx.x;
    const size_t nv = (size_t)nvec;

    if (i >= nvec) return;

    In5 cur, nxt;
    load5(impulse, mem, mem_acc, refrac_until, spikecounts, i, cur);

    for (; i < nvec; i += stride) {
        int j = i + stride;
        bool have_next = (j < nvec);
        if (have_next)
            load5(impulse, mem, mem_acc, refrac_until, spikecounts, j, nxt);

        compute_store(cur, out, nv, i);

        if (have_next) cur = nxt;
    }
}

extern "C" void kernel_launch(void* const* d_in, const int* in_sizes, int n_in,
                              void* d_out, int out_size)
{
    const float* impulse      = (const float*)d_in[0];
    const float* mem          = (const float*)d_in[1];
    const float* mem_acc      = (const float*)d_in[2];
    const float* refrac_until = (const float*)d_in[3];
    const float* spikecounts  = (const float*)d_in[4];

    int n = in_sizes[0];          // 12,845,056 — divisible by 4
    int nvec = n / 4;             // 3,211,264

    int threads = 256;
    int blocks = 148 * 8;         // one full wave, persistent grid-stride

    spike_layer_kernel<<<blocks, threads>>>(
        (const float4*)impulse,
        (const float4*)mem,
        (const float4*)mem_acc,
        (const float4*)refrac_until,
        (const float4*)spikecounts,
        (float4*)d_out,
        nvec);
}

// round 10
// speedup vs baseline: 1.0269x; 1.0269x over previous
#include <cuda_runtime.h>

// SpikeLayer LIF timestep, N = 12,845,056 fp32 elements, 5 inputs / 6 outputs.
// spikes ∈ {0,1}:
//   mem_out    = new_mem - spikes
//   counts_out = spikecounts + spikes
//   spiketrain = 0.5f * spikes
//   refrac_out = spikes ? 2.5f : refrac_until
//
// R5 (converged config): flat launch, VPT=2 processed sequentially per vec
// (keeps regs ~36 -> occ ~78%, unlike front-batched R2's 58 regs), grid=6272.
// Four prior experiments (occupancy, ILP, .cs hints, persistent pipeline) all
// pinned DRAM at ~80% / 6.4 TB/s -> this is the DRAM-scheduler ceiling for a
// 5-read/6-write interleaved stream. Kernel is at the memory roofline.

#define TIME_C 0.5f
#define VTH_C 1.0f
#define REFRAC_SET 2.5f
#define VPT 2

__global__ void __launch_bounds__(256) spike_layer_kernel(
    const float4* __restrict__ impulse,
    const float4* __restrict__ mem,
    const float4* __restrict__ mem_acc,
    const float4* __restrict__ refrac_until,
    const float4* __restrict__ spikecounts,
    float4* __restrict__ out,   // 6 * nvec float4s
    int nvec)
{
    const size_t nv = (size_t)nvec;
    int base = blockIdx.x * (256 * VPT) + threadIdx.x;

    #pragma unroll
    for (int v = 0; v < VPT; v++) {
        int i = base + v * 256;
        if (i >= nvec) return;

        float4 imp = impulse[i];
        float4 m   = mem[i];
        float4 ma  = mem_acc[i];
        float4 ru  = refrac_until[i];
        float4 sc  = spikecounts[i];

        float4 spikes, mem_out, ma_out, ru_out, sc_out, st_out;

        #pragma unroll
        for (int c = 0; c < 4; c++) {
            float impv = (&imp.x)[c];
            float mv   = (&m.x)[c];
            float mav  = (&ma.x)[c];
            float ruv  = (&ru.x)[c];
            float scv  = (&sc.x)[c];

            float masked  = (ruv > TIME_C) ? 0.0f : impv;
            float new_mem = mv + masked;
            float spk     = (new_mem >= VTH_C) ? 1.0f : 0.0f;

            (&spikes.x)[c]  = spk;
            (&mem_out.x)[c] = new_mem - spk;
            (&ma_out.x)[c]  = mav + masked;
            (&ru_out.x)[c]  = (spk != 0.0f) ? REFRAC_SET : ruv;
            (&sc_out.x)[c]  = scv + spk;
            (&st_out.x)[c]  = TIME_C * spk;
        }

        out[0 * nv + i] = spikes;
        out[1 * nv + i] = mem_out;
        out[2 * nv + i] = ma_out;
        out[3 * nv + i] = ru_out;
        out[4 * nv + i] = sc_out;
        out[5 * nv + i] = st_out;
    }
}

extern "C" void kernel_launch(void* const* d_in, const int* in_sizes, int n_in,
                              void* d_out, int out_size)
{
    const float* impulse      = (const float*)d_in[0];
    const float* mem          = (const float*)d_in[1];
    const float* mem_acc      = (const float*)d_in[2];
    const float* refrac_until = (const float*)d_in[3];
    const float* spikecounts  = (const float*)d_in[4];

    int n = in_sizes[0];          // 12,845,056 — divisible by 4
    int nvec = n / 4;             // 3,211,264

    int threads = 256;
    int per_block = threads * VPT;
    int blocks = (nvec + per_block - 1) / per_block;   // 6272

    spike_layer_kernel<<<blocks, threads>>>(
        (const float4*)impulse,
        (const float4*)mem,
        (const float4*)mem_acc,
        (const float4*)refrac_until,
        (const float4*)spikecounts,
        (float4*)d_out,
        nvec);
}

// round 13
// speedup vs baseline: 1.0355x; 1.0084x over previous
#include <cuda_runtime.h>

// SpikeLayer LIF timestep, elementwise over N = 16*56*56*256 = 12,845,056 fp32.
// Inputs: impulse, mem, mem_acc, refrac_until, spikecounts.
// Output: 6 stacked tensors [spikes, mem_out, mem_acc_out, refrac_out, counts_out, spiketrain].
//
// spikes ∈ {0,1}:
//   mem_out    = new_mem - spikes
//   counts_out = spikecounts + spikes
//   spiketrain = 0.5f * spikes
//   refrac_out = spikes ? 2.5f : refrac_until
//
// FINAL (R6 = R1 config): flat launch, one float4 per thread, 32 regs,
// occ ~78%. Five configurations tested (occupancy 41-78%, MLP 5-10,
// .cs streaming hints, persistent grid + SW pipeline, sequential VPT=2)
// all pin DRAM at 78.5-80.8% of the 8 TB/s spec (~6.3-6.4 TB/s). That is
// the DRAM-scheduler efficiency ceiling for this 5-read/6-write interleaved
// stream; this simplest config achieves the best kernel time (79.6 us).

#define TIME_C 0.5f
#define VTH_C 1.0f
#define REFRAC_SET 2.5f

__global__ void __launch_bounds__(256) spike_layer_kernel(
    const float4* __restrict__ impulse,
    const float4* __restrict__ mem,
    const float4* __restrict__ mem_acc,
    const float4* __restrict__ refrac_until,
    const float4* __restrict__ spikecounts,
    float4* __restrict__ out,   // 6 * nvec float4s
    int nvec)
{
    int i = blockIdx.x * blockDim.x + threadIdx.x;
    if (i >= nvec) return;

    float4 imp = impulse[i];
    float4 m   = mem[i];
    float4 ma  = mem_acc[i];
    float4 ru  = refrac_until[i];
    float4 sc  = spikecounts[i];

    float4 spikes, mem_out, ma_out, ru_out, sc_out, st_out;

    #pragma unroll
    for (int c = 0; c < 4; c++) {
        float impv = (&imp.x)[c];
        float mv   = (&m.x)[c];
        float mav  = (&ma.x)[c];
        float ruv  = (&ru.x)[c];
        float scv  = (&sc.x)[c];

        float masked  = (ruv > TIME_C) ? 0.0f : impv;
        float new_mem = mv + masked;
        float spk     = (new_mem >= VTH_C) ? 1.0f : 0.0f;

        (&spikes.x)[c]  = spk;
        (&mem_out.x)[c] = new_mem - spk;
        (&ma_out.x)[c]  = mav + masked;
        (&ru_out.x)[c]  = (spk != 0.0f) ? REFRAC_SET : ruv;
        (&sc_out.x)[c]  = scv + spk;
        (&st_out.x)[c]  = TIME_C * spk;
    }

    size_t nv = (size_t)nvec;
    out[0 * nv + i] = spikes;
    out[1 * nv + i] = mem_out;
    out[2 * nv + i] = ma_out;
    out[3 * nv + i] = ru_out;
    out[4 * nv + i] = sc_out;
    out[5 * nv + i] = st_out;
}

extern "C" void kernel_launch(void* const* d_in, const int* in_sizes, int n_in,
                              void* d_out, int out_size)
{
    const float* impulse      = (const float*)d_in[0];
    const float* mem          = (const float*)d_in[1];
    const float* mem_acc      = (const float*)d_in[2];
    const float* refrac_until = (const float*)d_in[3];
    const float* spikecounts  = (const float*)d_in[4];

    int n = in_sizes[0];          // 12,845,056 — divisible by 4
    int nvec = n / 4;             // 3,211,264 = 12,544 * 256 (no tail)

    int threads = 256;
    int blocks = (nvec + threads - 1) / threads;   // 12,544

    spike_layer_kernel<<<blocks, threads>>>(
        (const float4*)impulse,
        (const float4*)mem,
        (const float4*)mem_acc,
        (const float4*)refrac_until,
        (const float4*)spikecounts,
        (float4*)d_out,
        nvec);
}

// round 17
// speedup vs baseline: 1.0424x; 1.0066x over previous
#include <cuda_runtime.h>

// SpikeLayer LIF timestep, N = 12,845,056 fp32, 5 inputs / 6 outputs.
// spikes ∈ {0,1}:
//   mem_out    = new_mem - spikes
//   counts_out = spikecounts + spikes
//   spiketrain = 0.5f * spikes
//   refrac_out = spikes ? 2.5f : refrac_until
//
// R7: 256-bit global accesses (ld/st.global.v8.f32, sm_100+ PTX). Same bytes,
// half the L2/LSU transactions vs float4 — targets the LTS request-path cap
// (~6300 B/cyc) which matches our measured 6.36 TB/s plateau. 8 floats/thread,
// nvec8 = 1,605,632 = 6272 x 256 (zero tail).

#define TIME_C 0.5f
#define VTH_C 1.0f
#define REFRAC_SET 2.5f

__device__ __forceinline__ void ldg256(const float* __restrict__ p, float r[8]) {
    asm volatile("ld.global.v8.f32 {%0,%1,%2,%3,%4,%5,%6,%7}, [%8];"
                 : "=f"(r[0]), "=f"(r[1]), "=f"(r[2]), "=f"(r[3]),
                   "=f"(r[4]), "=f"(r[5]), "=f"(r[6]), "=f"(r[7])
                 : "l"(p));
}

__device__ __forceinline__ void stg256(float* __restrict__ p, const float r[8]) {
    asm volatile("st.global.v8.f32 [%0], {%1,%2,%3,%4,%5,%6,%7,%8};"
                 :: "l"(p),
                    "f"(r[0]), "f"(r[1]), "f"(r[2]), "f"(r[3]),
                    "f"(r[4]), "f"(r[5]), "f"(r[6]), "f"(r[7])
                 : "memory");
}

__global__ void __launch_bounds__(256) spike_layer_kernel(
    const float* __restrict__ impulse,
    const float* __restrict__ mem,
    const float* __restrict__ mem_acc,
    const float* __restrict__ refrac_until,
    const float* __restrict__ spikecounts,
    float* __restrict__ out,   // 6 * n floats
    int nvec8)                 // number of 8-float vectors
{
    int i = blockIdx.x * blockDim.x + threadIdx.x;
    if (i >= nvec8) return;

    const size_t off = (size_t)i * 8;
    const size_t n   = (size_t)nvec8 * 8;

    float imp[8], m[8], ma[8], ru[8], sc[8];
    ldg256(impulse      + off, imp);
    ldg256(mem          + off, m);
    ldg256(mem_acc      + off, ma);
    ldg256(refrac_until + off, ru);
    ldg256(spikecounts  + off, sc);

    float spikes[8], mem_out[8], ma_out[8], ru_out[8], sc_out[8], st_out[8];

    #pragma unroll
    for (int c = 0; c < 8; c++) {
        float masked  = (ru[c] > TIME_C) ? 0.0f : imp[c];
        float new_mem = m[c] + masked;
        float spk     = (new_mem >= VTH_C) ? 1.0f : 0.0f;

        spikes[c]  = spk;
        mem_out[c] = new_mem - spk;
        ma_out[c]  = ma[c] + masked;
        ru_out[c]  = (spk != 0.0f) ? REFRAC_SET : ru[c];
        sc_out[c]  = sc[c] + spk;
        st_out[c]  = TIME_C * spk;
    }

    stg256(out + 0 * n + off, spikes);
    stg256(out + 1 * n + off, mem_out);
    stg256(out + 2 * n + off, ma_out);
    stg256(out + 3 * n + off, ru_out);
    stg256(out + 4 * n + off, sc_out);
    stg256(out + 5 * n + off, st_out);
}

extern "C" void kernel_launch(void* const* d_in, const int* in_sizes, int n_in,
                              void* d_out, int out_size)
{
    const float* impulse      = (const float*)d_in[0];
    const float* mem          = (const float*)d_in[1];
    const float* mem_acc      = (const float*)d_in[2];
    const float* refrac_until = (const float*)d_in[3];
    const float* spikecounts  = (const float*)d_in[4];

    int n = in_sizes[0];          // 12,845,056 — divisible by 8
    int nvec8 = n / 8;            // 1,605,632 = 6272 * 256 (no tail)

    int threads = 256;
    int blocks = (nvec8 + threads - 1) / threads;   // 6272

    spike_layer_kernel<<<blocks, threads>>>(
        impulse, mem, mem_acc, refrac_until, spikecounts,
        (float*)d_out, nvec8);
}